// round 16
// baseline (speedup 1.0000x reference)
#include <cuda_runtime.h>
#include <math.h>

// ---------------- scratch (no allocation allowed) ----------------
#define MAXN   262144
#define CHUNK  128                     // segments per pass1 block
#define MAXC   (MAXN / CHUNK)          // 2048 chunks
#define FULL   0xffffffffu
__device__ int    g_csum[MAXC];      // per-chunk count sums
__device__ int    g_cbase[MAXC];     // exclusive chunk bases
__device__ double g_acc[4];          // lp, la, lw, ls sums
__device__ int    g_done = 0;        // completion counter for folded finalize

// ------ kernel A: per-chunk sums (one warp per chunk, int4 + redux) -----------
__global__ void __launch_bounds__(256) k_csum(const int* __restrict__ counts, int N, int NC) {
    int w    = (blockIdx.x * blockDim.x + threadIdx.x) >> 5;   // global warp = chunk
    int lane = threadIdx.x & 31;
    if (w >= NC) return;
    int base = w * CHUNK + lane * 4;
    int4 v = make_int4(0, 0, 0, 0);
    if (base + 3 < N) v = *(const int4*)(counts + base);
    else {
        if (base + 0 < N) v.x = counts[base + 0];
        if (base + 1 < N) v.y = counts[base + 1];
        if (base + 2 < N) v.z = counts[base + 2];
        if (base + 3 < N) v.w = counts[base + 3];
    }
    int s = __reduce_add_sync(FULL, v.x + v.y + v.z + v.w);
    if (lane == 0) g_csum[w] = s;
}

// ------ kernel B: scan chunk sums (single block, 512 thr x 4) -----------------
__global__ void __launch_bounds__(512) k_cscan(int NC) {
    __shared__ int wsum[16];
    int tid = threadIdx.x, lane = tid & 31, w = tid >> 5;
    int i0 = tid * 4;
    int v0 = (i0 + 0 < NC) ? g_csum[i0 + 0] : 0;
    int v1 = (i0 + 1 < NC) ? g_csum[i0 + 1] : 0;
    int v2 = (i0 + 2 < NC) ? g_csum[i0 + 2] : 0;
    int v3 = (i0 + 3 < NC) ? g_csum[i0 + 3] : 0;
    int s = v0 + v1 + v2 + v3;

    int si = s;
    #pragma unroll
    for (int o = 1; o < 32; o <<= 1) {
        int t = __shfl_up_sync(FULL, si, o);
        if (lane >= o) si += t;
    }
    if (lane == 31) wsum[w] = si;
    __syncthreads();
    if (w == 0) {
        int ws = (lane < 16) ? wsum[lane] : 0;
        int wi = ws;
        #pragma unroll
        for (int o = 1; o < 16; o <<= 1) {
            int t = __shfl_up_sync(FULL, wi, o);
            if (lane >= o) wi += t;
        }
        if (lane < 16) wsum[lane] = wi - ws;   // exclusive warp offset
    }
    __syncthreads();

    int b = wsum[w] + (si - s);                // global exclusive base of thread's 4
    if (i0 + 0 < NC) g_cbase[i0 + 0] = b;       b += v0;
    if (i0 + 1 < NC) g_cbase[i0 + 1] = b;       b += v1;
    if (i0 + 2 < NC) g_cbase[i0 + 2] = b;       b += v2;
    if (i0 + 3 < NC) g_cbase[i0 + 3] = b;
    if (tid < 4) g_acc[tid] = 0.0;
}

// ------ pass 1: block = 128 segments; argmin loop + fused loss epilogue -------
__device__ __forceinline__ void p1_seg(
    const float* __restrict__ pred, const float* __restrict__ gt,
    const int* __restrict__ s_off, int gbase, int j, int M, int N, int lane,
    int& off, int& cnt, float2& p01, int& r)
{
    off = s_off[j]; cnt = s_off[j + 1] - off;
    int s = gbase + j;
    p01 = (s < N) ? *(const float2*)(pred + (size_t)s * 6) : make_float2(0.f, 0.f);
    r = off + ((lane < cnt) ? lane : 0);
    r = min(r, M - 1);
}

__global__ void __launch_bounds__(256) k_pass1(
    const float* __restrict__ pred,
    const float* __restrict__ gt,
    const int*   __restrict__ counts,
    float* __restrict__ out,
    int N, int M)
{
    __shared__ int      s_off[CHUNK + 1];
    __shared__ int      s_wtot[4];
    __shared__ int      s_row[CHUNK];    // winner row + 1, or 0 (no gt)
    __shared__ unsigned s_db[CHUNK];     // winner dist bits
    const int tid  = threadIdx.x;
    const int lane = tid & 31;
    const int gbase = blockIdx.x * CHUNK;

    // local exclusive scan of this block's 128 counts
    if (tid < CHUNK) {
        int w = tid >> 5;
        int g = gbase + tid;
        int c = (g < N) ? counts[g] : 0;
        int inc = c;
        #pragma unroll
        for (int o = 1; o < 32; o <<= 1) {
            int t = __shfl_up_sync(FULL, inc, o);
            if (lane >= o) inc += t;
        }
        if (lane == 31) s_wtot[w] = inc;
        __syncthreads();
        int woff = 0;
        #pragma unroll
        for (int i = 0; i < 4; i++) woff += (i < w) ? s_wtot[i] : 0;
        int cbase = g_cbase[blockIdx.x];
        s_off[tid] = cbase + woff + inc - c;
        if (tid == CHUNK - 1) s_off[CHUNK] = cbase + woff + inc;
    } else {
        __syncthreads();
    }
    __syncthreads();

    // 8 warps x 16 consecutive segments each — argmin only
    const int wInBlk = tid >> 5;
    const int wbase  = wInBlk * 16;

    #pragma unroll
    for (int k = 0; k < 16; k += 2) {
        int off0, cnt0, off1, cnt1, r0, r1; float2 p0, p1;
        p1_seg(pred, gt, s_off, gbase, wbase + k,     M, N, lane, off0, cnt0, p0, r0);
        p1_seg(pred, gt, s_off, gbase, wbase + k + 1, M, N, lane, off1, cnt1, p1, r1);

        float2 q0 = *(const float2*)(gt + (size_t)r0 * 6);   // 2 loads in flight
        float2 q1 = *(const float2*)(gt + (size_t)r1 * 6);

        float dx0 = p0.x - q0.x, dy0 = p0.y - q0.y;
        float dx1 = p1.x - q1.x, dy1 = p1.y - q1.y;
        unsigned db0 = (lane < cnt0) ? __float_as_uint(dx0 * dx0 + dy0 * dy0) : 0x7f800000u;
        unsigned db1 = (lane < cnt1) ? __float_as_uint(dx1 * dx1 + dy1 * dy1) : 0x7f800000u;

        unsigned mn0 = __reduce_min_sync(FULL, db0);
        unsigned mk0 = __ballot_sync(FULL, db0 == mn0);   // lowest lane = ref tie-break
        unsigned mn1 = __reduce_min_sync(FULL, db1);
        unsigned mk1 = __ballot_sync(FULL, db1 == mn1);

        if (lane == 0) {
            s_row[wbase + k]     = (cnt0 > 0) ? off0 + __ffs(mk0) : 0;
            s_db [wbase + k]     = mn0;
            s_row[wbase + k + 1] = (cnt1 > 0) ? off1 + __ffs(mk1) : 0;
            s_db [wbase + k + 1] = mn1;
        }
    }
    __syncthreads();

    // ---- fused loss epilogue: threads 0-127, one segment each (gt rows L1-hot)
    float l0 = 0.f, l1 = 0.f, l2 = 0.f, l3 = 0.f;
    if (tid < CHUNK) {
        int s = gbase + tid;
        int wr = s_row[tid];
        if (s < N && wr > 0) {
            int row = wr - 1;
            float dmin = __uint_as_float(s_db[tid]);
            l0 = 1.0f - __expf(dmin * (-1.0f / 0.045f));   // 2*sigma^2 = 0.045

            const float* pr = pred + (size_t)s * 6;        // L1/L2-hot (just streamed)
            const float* gr = gt + (size_t)row * 6;        // L1-hot (this block's span)
            float2 p23 = *(const float2*)(pr + 2);
            float2 p45 = *(const float2*)(pr + 4);
            float2 g23 = *(const float2*)(gr + 2);
            float2 g45 = *(const float2*)(gr + 4);

            l1 = fabsf(p23.x - g23.x) + fabsf(p23.y - g23.y);
            float dd = p45.x - g45.x, ad = fabsf(dd);
            l2 = (ad < 1.0f) ? 0.5f * dd * dd : ad - 0.5f;
            float x = p45.y, t = g45.y;
            if (t > 0.0f) {
                float z = __expf(-fabsf(x));
                l3 = fmaxf(x, 0.0f) - x * t + __logf(1.0f + z);
            }
        }
    }

    // block reduce over all 256 threads (upper 128 contribute zero)
    #pragma unroll
    for (int o = 16; o; o >>= 1) {
        l0 += __shfl_xor_sync(FULL, l0, o);
        l1 += __shfl_xor_sync(FULL, l1, o);
        l2 += __shfl_xor_sync(FULL, l2, o);
        l3 += __shfl_xor_sync(FULL, l3, o);
    }
    __shared__ float sh[8][4];
    if (lane == 0) {
        sh[wInBlk][0] = l0; sh[wInBlk][1] = l1;
        sh[wInBlk][2] = l2; sh[wInBlk][3] = l3;
    }
    __syncthreads();
    if (tid == 0) {
        float b0 = 0.f, b1 = 0.f, b2 = 0.f, b3 = 0.f;
        #pragma unroll
        for (int w = 0; w < 8; w++) {
            b0 += sh[w][0]; b1 += sh[w][1]; b2 += sh[w][2]; b3 += sh[w][3];
        }
        atomicAdd(&g_acc[0], (double)b0);
        atomicAdd(&g_acc[1], (double)b1);
        atomicAdd(&g_acc[2], (double)b2);
        atomicAdd(&g_acc[3], (double)b3);
        __threadfence();
        int done = atomicAdd(&g_done, 1);
        if (done == (int)gridDim.x - 1) {
            g_done = 0;                               // reset for next replay
            double inv = 1.0 / (double)N;
            double lp = ((volatile double*)g_acc)[0] * inv;
            double la = ((volatile double*)g_acc)[1] * inv;
            double lw = ((volatile double*)g_acc)[2] * inv;
            double ls = ((volatile double*)g_acc)[3] * inv;
            out[0] = (float)lp;
            out[1] = (float)la;
            out[2] = (float)lw;
            out[3] = (float)ls;
            out[4] = (float)(lp + la + lw + 0.5 * ls);
        }
    }
}

extern "C" void kernel_launch(void* const* d_in, const int* in_sizes, int n_in,
                              void* d_out, int out_size) {
    const float* pred   = (const float*)d_in[0];
    const float* gt     = (const float*)d_in[1];
    const int*   counts = (const int*)d_in[2];
    float* out = (float*)d_out;

    int N = in_sizes[2];
    if (N > MAXN) N = MAXN;              // scratch guard (contract: N == 262144)
    int M = in_sizes[1] / 6;             // total gt rows
    int NC = (N + CHUNK - 1) / CHUNK;    // chunks (2048)

    k_csum <<<(NC + 7) / 8, 256>>>(counts, N, NC);      // 8 warps/block = 8 chunks
    k_cscan<<<1, 512>>>(NC);
    k_pass1<<<NC, 256>>>(pred, gt, counts, out, N, M);
}

// round 17
// speedup vs baseline: 1.0777x; 1.0777x over previous
#include <cuda_runtime.h>
#include <math.h>

// ---------------- scratch (no allocation allowed) ----------------
#define MAXN   262144
#define CHUNK  128                     // segments per chunk
#define MAXC   (MAXN / CHUNK)          // 2048 chunks
#define SLOTS  4                       // max chunks per block (ceil(2048/592))
#define GRID2  592
#define FULL   0xffffffffu
__device__ int    g_csum[MAXC];      // per-chunk count sums
__device__ double g_acc[4];          // lp, la, lw, ls sums
__device__ int    g_done = 0;        // completion counter for folded finalize

// ------ kernel A: per-chunk sums (one warp per chunk) + zero accumulators -----
__global__ void __launch_bounds__(256) k_csum(const int* __restrict__ counts, int N, int NC) {
    if (blockIdx.x == 0 && threadIdx.x < 4) g_acc[threadIdx.x] = 0.0;
    int w    = (blockIdx.x * blockDim.x + threadIdx.x) >> 5;   // global warp = chunk
    int lane = threadIdx.x & 31;
    if (w >= NC) return;
    int base = w * CHUNK + lane * 4;
    int4 v = make_int4(0, 0, 0, 0);
    if (base + 3 < N) v = *(const int4*)(counts + base);
    else {
        if (base + 0 < N) v.x = counts[base + 0];
        if (base + 1 < N) v.y = counts[base + 1];
        if (base + 2 < N) v.z = counts[base + 2];
        if (base + 3 < N) v.w = counts[base + 3];
    }
    int s = __reduce_add_sync(FULL, v.x + v.y + v.z + v.w);
    if (lane == 0) g_csum[w] = s;
}

// ------ kernel B: fused prefix + argmin + loss epilogue + finalize ------------
__global__ void __launch_bounds__(256) k_fused(
    const float* __restrict__ pred,
    const float* __restrict__ gt,
    const int*   __restrict__ counts,
    float* __restrict__ out,
    int N, int M, int NC)
{
    __shared__ int      s_off[CHUNK + 1];
    __shared__ int      s_wtot[4];
    __shared__ int      s_base[SLOTS];
    __shared__ int      s_row[SLOTS * CHUNK];    // winner row + 1, or 0
    __shared__ unsigned s_db[SLOTS * CHUNK];     // winner dist bits
    __shared__ float    sh[8][4];

    const int tid  = threadIdx.x;
    const int lane = tid & 31;
    const int wIB  = tid >> 5;
    const int B = blockIdx.x, G = gridDim.x;

    // ---- inline prefix: base of chunk c_k = B + k*G  (sum of g_csum[0..c_k))
    {
        int c0 = B, c1 = B + G, c2 = B + 2 * G, c3 = B + 3 * G;
        int a0 = 0, a1 = 0, a2 = 0, a3 = 0;
        for (int i = tid; i < NC; i += 256) {
            int v = g_csum[i];
            a0 += (i < c0) ? v : 0;
            a1 += (i < c1) ? v : 0;
            a2 += (i < c2) ? v : 0;
            a3 += (i < c3) ? v : 0;
        }
        #pragma unroll
        for (int o = 16; o; o >>= 1) {
            a0 += __shfl_xor_sync(FULL, a0, o);
            a1 += __shfl_xor_sync(FULL, a1, o);
            a2 += __shfl_xor_sync(FULL, a2, o);
            a3 += __shfl_xor_sync(FULL, a3, o);
        }
        if (lane == 0) {
            s_row[wIB * 4 + 0] = a0; s_row[wIB * 4 + 1] = a1;
            s_row[wIB * 4 + 2] = a2; s_row[wIB * 4 + 3] = a3;
        }
        __syncthreads();
        if (tid < SLOTS) {
            int t = 0;
            #pragma unroll
            for (int w2 = 0; w2 < 8; w2++) t += s_row[w2 * 4 + tid];
            s_base[tid] = t;
        }
        __syncthreads();
    }

    // ---- chunk loop: local scan + warp argmin, winners to smem ----
    for (int k = 0; k < SLOTS; k++) {
        int c = B + k * G;
        if (c >= NC) break;                       // uniform across block
        int gbase = c * CHUNK;
        __syncthreads();                          // s_off reuse guard
        if (tid < CHUNK) {
            int g = gbase + tid;
            int cc = (g < N) ? counts[g] : 0;
            int inc = cc;
            #pragma unroll
            for (int o = 1; o < 32; o <<= 1) {
                int t = __shfl_up_sync(FULL, inc, o);
                if (lane >= o) inc += t;
            }
            if (lane == 31) s_wtot[tid >> 5] = inc;
            __syncthreads();
            int woff = 0;
            #pragma unroll
            for (int i = 0; i < 4; i++) woff += (i < (tid >> 5)) ? s_wtot[i] : 0;
            s_off[tid] = s_base[k] + woff + inc - cc;
            if (tid == CHUNK - 1) s_off[CHUNK] = s_base[k] + woff + inc;
        } else {
            __syncthreads();
        }
        __syncthreads();

        const int wbase = wIB * 16;
        #pragma unroll
        for (int kk = 0; kk < 16; kk += 2) {
            int j0 = wbase + kk, j1 = wbase + kk + 1;
            int off0 = s_off[j0], cnt0 = s_off[j0 + 1] - off0;
            int off1 = s_off[j1], cnt1 = s_off[j1 + 1] - off1;
            int sg0 = gbase + j0, sg1 = gbase + j1;
            float2 p0 = (sg0 < N) ? *(const float2*)(pred + (size_t)sg0 * 6) : make_float2(0.f, 0.f);
            float2 p1 = (sg1 < N) ? *(const float2*)(pred + (size_t)sg1 * 6) : make_float2(0.f, 0.f);
            int r0 = min(off0 + ((lane < cnt0) ? lane : 0), M - 1);
            int r1 = min(off1 + ((lane < cnt1) ? lane : 0), M - 1);

            float2 q0 = *(const float2*)(gt + (size_t)r0 * 6);   // 2 loads in flight
            float2 q1 = *(const float2*)(gt + (size_t)r1 * 6);

            float dx0 = p0.x - q0.x, dy0 = p0.y - q0.y;
            float dx1 = p1.x - q1.x, dy1 = p1.y - q1.y;
            unsigned db0 = (lane < cnt0) ? __float_as_uint(dx0 * dx0 + dy0 * dy0) : 0x7f800000u;
            unsigned db1 = (lane < cnt1) ? __float_as_uint(dx1 * dx1 + dy1 * dy1) : 0x7f800000u;

            unsigned mn0 = __reduce_min_sync(FULL, db0);
            unsigned mk0 = __ballot_sync(FULL, db0 == mn0);   // lowest lane = ref tie-break
            unsigned mn1 = __reduce_min_sync(FULL, db1);
            unsigned mk1 = __ballot_sync(FULL, db1 == mn1);

            if (lane == 0) {
                s_row[k * CHUNK + j0] = (cnt0 > 0) ? off0 + __ffs(mk0) : 0;
                s_db [k * CHUNK + j0] = mn0;
                s_row[k * CHUNK + j1] = (cnt1 > 0) ? off1 + __ffs(mk1) : 0;
                s_db [k * CHUNK + j1] = mn1;
            }
        }
    }
    __syncthreads();

    // ---- epilogue: 2 segments/thread, 8 batched loads (gt tails L2-warm) ----
    float l0 = 0.f, l1 = 0.f, l2 = 0.f, l3 = 0.f;
    {
        int e0 = tid, e1 = tid + 256;
        int sl0 = e0 >> 7, sl1 = e1 >> 7;
        int c0 = B + sl0 * G, c1 = B + sl1 * G;
        int s0 = c0 * CHUNK + (e0 & 127), s1 = c1 * CHUNK + (e1 & 127);
        int wr0 = (c0 < NC) ? s_row[e0] : 0;
        int wr1 = (c1 < NC) ? s_row[e1] : 0;
        bool v0 = (c0 < NC) && (s0 < N) && (wr0 > 0);
        bool v1 = (c1 < NC) && (s1 < N) && (wr1 > 0);
        unsigned d0 = v0 ? s_db[e0] : 0u;
        unsigned d1 = v1 ? s_db[e1] : 0u;
        int r0 = max(wr0 - 1, 0), r1 = max(wr1 - 1, 0);
        int q0 = v0 ? s0 : 0,     q1 = v1 ? s1 : 0;

        const float* pr0 = pred + (size_t)q0 * 6; const float* gr0 = gt + (size_t)r0 * 6;
        const float* pr1 = pred + (size_t)q1 * 6; const float* gr1 = gt + (size_t)r1 * 6;
        float2 pa0 = *(const float2*)(pr0 + 2), pb0 = *(const float2*)(pr0 + 4);
        float2 pa1 = *(const float2*)(pr1 + 2), pb1 = *(const float2*)(pr1 + 4);
        float2 ga0 = *(const float2*)(gr0 + 2), gb0 = *(const float2*)(gr0 + 4);
        float2 ga1 = *(const float2*)(gr1 + 2), gb1 = *(const float2*)(gr1 + 4);

        {
            float f = v0 ? 1.0f : 0.0f;
            float dmin = __uint_as_float(d0);
            l0 += f * (1.0f - __expf(dmin * (-1.0f / 0.045f)));    // 2*sigma^2 = 0.045
            l1 += f * (fabsf(pa0.x - ga0.x) + fabsf(pa0.y - ga0.y));
            float dd = pb0.x - gb0.x, ad = fabsf(dd);
            l2 += f * ((ad < 1.0f) ? 0.5f * dd * dd : ad - 0.5f);
            float x = pb0.y, t = gb0.y;
            if (v0 && t > 0.0f)
                l3 += fmaxf(x, 0.0f) - x * t + __logf(1.0f + __expf(-fabsf(x)));
        }
        {
            float f = v1 ? 1.0f : 0.0f;
            float dmin = __uint_as_float(d1);
            l0 += f * (1.0f - __expf(dmin * (-1.0f / 0.045f)));
            l1 += f * (fabsf(pa1.x - ga1.x) + fabsf(pa1.y - ga1.y));
            float dd = pb1.x - gb1.x, ad = fabsf(dd);
            l2 += f * ((ad < 1.0f) ? 0.5f * dd * dd : ad - 0.5f);
            float x = pb1.y, t = gb1.y;
            if (v1 && t > 0.0f)
                l3 += fmaxf(x, 0.0f) - x * t + __logf(1.0f + __expf(-fabsf(x)));
        }
    }

    // ---- block reduce + global accumulate + folded finalize ----
    #pragma unroll
    for (int o = 16; o; o >>= 1) {
        l0 += __shfl_xor_sync(FULL, l0, o);
        l1 += __shfl_xor_sync(FULL, l1, o);
        l2 += __shfl_xor_sync(FULL, l2, o);
        l3 += __shfl_xor_sync(FULL, l3, o);
    }
    if (lane == 0) {
        sh[wIB][0] = l0; sh[wIB][1] = l1;
        sh[wIB][2] = l2; sh[wIB][3] = l3;
    }
    __syncthreads();
    if (tid == 0) {
        float b0 = 0.f, b1 = 0.f, b2 = 0.f, b3 = 0.f;
        #pragma unroll
        for (int w2 = 0; w2 < 8; w2++) {
            b0 += sh[w2][0]; b1 += sh[w2][1]; b2 += sh[w2][2]; b3 += sh[w2][3];
        }
        atomicAdd(&g_acc[0], (double)b0);
        atomicAdd(&g_acc[1], (double)b1);
        atomicAdd(&g_acc[2], (double)b2);
        atomicAdd(&g_acc[3], (double)b3);
        __threadfence();
        int done = atomicAdd(&g_done, 1);
        if (done == (int)gridDim.x - 1) {
            g_done = 0;                               // reset for next replay
            double inv = 1.0 / (double)N;
            double lp = ((volatile double*)g_acc)[0] * inv;
            double la = ((volatile double*)g_acc)[1] * inv;
            double lw = ((volatile double*)g_acc)[2] * inv;
            double ls = ((volatile double*)g_acc)[3] * inv;
            out[0] = (float)lp;
            out[1] = (float)la;
            out[2] = (float)lw;
            out[3] = (float)ls;
            out[4] = (float)(lp + la + lw + 0.5 * ls);
        }
    }
}

extern "C" void kernel_launch(void* const* d_in, const int* in_sizes, int n_in,
                              void* d_out, int out_size) {
    const float* pred   = (const float*)d_in[0];
    const float* gt     = (const float*)d_in[1];
    const int*   counts = (const int*)d_in[2];
    float* out = (float*)d_out;

    int N = in_sizes[2];
    if (N > MAXN) N = MAXN;              // scratch guard (contract: N == 262144)
    int M = in_sizes[1] / 6;             // total gt rows
    int NC = (N + CHUNK - 1) / CHUNK;    // chunks (2048)

    k_csum <<<(NC + 7) / 8, 256>>>(counts, N, NC);
    k_fused<<<GRID2, 256>>>(pred, gt, counts, out, N, M, NC);
}